// round 2
// baseline (speedup 1.0000x reference)
#include <cuda_runtime.h>
#include <cstdint>

// naivePC: DP over (k,m) lattice, K=8, N=20.
// Column-sweep: S(k,m) = w0[k][m]*S(k,m-1) + w1[k][m]*S(k-1,m-1)*x[m-1]
// base S(k,k) = prod of first k bits; leaf S(1,m) = [popcnt(bits[0:m])==1]*wsm[m][idx]

#define NCOL 20
#define KMAX 8
#define ROWS_PER_THREAD 4

__device__ int g_elem4;   // 1 if x elements are 4 bytes (float32/int32), 0 if 1 byte (bool)

__global__ void detect_kernel(const unsigned char* __restrict__ xb, int nscan)
{
    __shared__ int sGT1, sNZ123, sNZ0;
    if (threadIdx.x == 0) { sGT1 = 0; sNZ123 = 0; sNZ0 = 0; }
    __syncthreads();
    int aGT1 = 0, aNZ123 = 0, aNZ0 = 0;
    for (int i = threadIdx.x; i < nscan; i += blockDim.x) {
        unsigned char b = xb[i];
        if (b > 1) aGT1 = 1;
        if (b != 0) { if ((i & 3) == 0) aNZ0 = 1; else aNZ123 = 1; }
    }
    if (aGT1)   atomicOr(&sGT1, 1);
    if (aNZ123) atomicOr(&sNZ123, 1);
    if (aNZ0)   atomicOr(&sNZ0, 1);
    __syncthreads();
    if (threadIdx.x == 0) {
        // float32 has bytes 0x80/0x3F  -> GT1.
        // int32 {0,1}: nonzero only at offset%4==0.
        // bool bytes {0,1}: nonzero at arbitrary offsets.
        g_elem4 = (sGT1 || (sNZ0 && !sNZ123)) ? 1 : 0;
    }
}

__global__ __launch_bounds__(256)
void pc_kernel(const unsigned char* __restrict__ xb,
               const float* __restrict__ Wleaf,   // [21][20]
               const float* __restrict__ W2,      // [9][21][2]
               float* __restrict__ out,
               int B)
{
    __shared__ float s_wsm[21 * 32];   // stride 32: conflict-free dynamic gather
    __shared__ float s_w0[9 * 21];
    __shared__ float s_w1[9 * 21];

    const int tid = threadIdx.x;

    // ---- cooperative weight precompute (tiny) ----
    if (tid < 21) {
        int m = tid;
        float mx = -1e30f;
        for (int i = 0; i < m; i++) mx = fmaxf(mx, Wleaf[m * 20 + i]);
        float Z = 0.0f;
        for (int i = 0; i < m; i++) Z += expf(Wleaf[m * 20 + i] - mx);
        float inv = (m > 0) ? (1.0f / Z) : 0.0f;
        for (int i = 0; i < 32; i++) {
            float v = 0.0f;
            if (i < m) v = expf(Wleaf[m * 20 + i] - mx) * inv;
            s_wsm[m * 32 + i] = v;
        }
    }
    if (tid >= 32 && tid < 32 + 9 * 21) {
        int j = tid - 32;
        float a = W2[j * 2 + 0];
        float b = W2[j * 2 + 1];
        float mx = fmaxf(a, b);
        float e0 = expf(a - mx), e1 = expf(b - mx);
        float inv = 1.0f / (e0 + e1);
        s_w0[j] = e0 * inv;
        s_w1[j] = e1 * inv;
    }
    __syncthreads();

    const long g = (long)blockIdx.x * blockDim.x + tid;   // group of 4 rows
    const long base = g * ROWS_PER_THREAD;
    if (base >= B) return;

    const int elem4 = g_elem4;

    // ---- build 20-bit masks for 4 rows ----
    unsigned mask[ROWS_PER_THREAD] = {0, 0, 0, 0};
    if (elem4) {
        // 4-byte elements (float32 or int32): truth == word != 0
        if (base + ROWS_PER_THREAD <= (long)B) {
            const uint4* p = reinterpret_cast<const uint4*>(xb) + base * 5; // 20 words = 5 uint4 / row
            #pragma unroll
            for (int r = 0; r < ROWS_PER_THREAD; r++) {
                unsigned mres = 0;
                #pragma unroll
                for (int j = 0; j < 5; j++) {
                    uint4 q = p[r * 5 + j];
                    mres |= (unsigned)(q.x != 0u) << (4 * j + 0);
                    mres |= (unsigned)(q.y != 0u) << (4 * j + 1);
                    mres |= (unsigned)(q.z != 0u) << (4 * j + 2);
                    mres |= (unsigned)(q.w != 0u) << (4 * j + 3);
                }
                mask[r] = mres;
            }
        } else {
            const unsigned* p = reinterpret_cast<const unsigned*>(xb);
            #pragma unroll
            for (int r = 0; r < ROWS_PER_THREAD; r++) {
                unsigned mres = 0;
                if (base + r < (long)B)
                    for (int m = 0; m < 20; m++)
                        mres |= (unsigned)(p[(base + r) * 20 + m] != 0u) << m;
                mask[r] = mres;
            }
        }
    } else {
        // 1-byte bool elements
        if (base + ROWS_PER_THREAD <= (long)B) {
            const uint4* p = reinterpret_cast<const uint4*>(xb + base * 20);
            uint4 q0 = p[0], q1 = p[1], q2 = p[2], q3 = p[3], q4 = p[4];
            unsigned w[20] = { q0.x, q0.y, q0.z, q0.w,
                               q1.x, q1.y, q1.z, q1.w,
                               q2.x, q2.y, q2.z, q2.w,
                               q3.x, q3.y, q3.z, q3.w,
                               q4.x, q4.y, q4.z, q4.w };
            #pragma unroll
            for (int r = 0; r < ROWS_PER_THREAD; r++) {
                unsigned mres = 0;
                #pragma unroll
                for (int j = 0; j < 5; j++) {
                    unsigned b = w[r * 5 + j] & 0x01010101u;
                    unsigned nib = ((b * 0x01020408u) >> 24) & 0xFu;
                    mres |= nib << (4 * j);
                }
                mask[r] = mres;
            }
        } else {
            #pragma unroll
            for (int r = 0; r < ROWS_PER_THREAD; r++) {
                unsigned mres = 0;
                if (base + r < (long)B)
                    for (int m = 0; m < 20; m++)
                        mres |= (unsigned)(xb[(base + r) * 20 + m] & 1) << m;
                mask[r] = mres;
            }
        }
    }

    // ---- column-sweep DP, 4 rows interleaved ----
    float S[ROWS_PER_THREAD][KMAX + 1];
    #pragma unroll
    for (int r = 0; r < ROWS_PER_THREAD; r++)
        #pragma unroll
        for (int k = 0; k <= KMAX; k++) S[r][k] = 0.0f;

    int cnt[ROWS_PER_THREAD] = {0, 0, 0, 0};
    int idx[ROWS_PER_THREAD] = {0, 0, 0, 0};
    unsigned pf[ROWS_PER_THREAD] = {1u, 1u, 1u, 1u};

    #pragma unroll
    for (int m = 1; m <= NCOL; m++) {
        unsigned bit[ROWS_PER_THREAD];
        #pragma unroll
        for (int r = 0; r < ROWS_PER_THREAD; r++) {
            bit[r] = (mask[r] >> (m - 1)) & 1u;
            cnt[r] += (int)bit[r];
            idx[r] = bit[r] ? (m - 1) : idx[r];
        }
        if (m <= KMAX) {
            #pragma unroll
            for (int r = 0; r < ROWS_PER_THREAD; r++) pf[r] &= bit[r];
        }

        const int kmax = (m < KMAX) ? m : KMAX;
        #pragma unroll
        for (int k = KMAX; k >= 2; k--) {
            if (k > kmax) continue;              // folds at compile time
            if (k == m) {
                #pragma unroll
                for (int r = 0; r < ROWS_PER_THREAD; r++)
                    S[r][k] = pf[r] ? 1.0f : 0.0f;
            } else {
                const float w0v = s_w0[k * 21 + m];
                const float w1v = s_w1[k * 21 + m];
                #pragma unroll
                for (int r = 0; r < ROWS_PER_THREAD; r++) {
                    float u = w0v * S[r][k];
                    S[r][k] = bit[r] ? fmaf(w1v, S[r][k - 1], u) : u;
                }
            }
        }
        // leaf level S(1,m) — written AFTER its use at this column
        #pragma unroll
        for (int r = 0; r < ROWS_PER_THREAD; r++) {
            float s = s_wsm[m * 32 + idx[r]];
            S[r][1] = (cnt[r] == 1) ? s : 0.0f;
        }
    }

    #pragma unroll
    for (int r = 0; r < ROWS_PER_THREAD; r++)
        if (base + r < (long)B) out[base + r] = S[r][KMAX];
}

extern "C" void kernel_launch(void* const* d_in, const int* in_sizes, int n_in,
                              void* d_out, int out_size)
{
    const unsigned char* x = (const unsigned char*)d_in[0];
    const float* Wleaf = (const float*)d_in[1];
    const float* W2 = (const float*)d_in[2];
    float* out = (float*)d_out;

    const int B = in_sizes[0] / NCOL;

    int nscan = in_sizes[0] < 8192 ? in_sizes[0] : 8192;
    detect_kernel<<<1, 256>>>(x, nscan);

    const long groups = ((long)B + ROWS_PER_THREAD - 1) / ROWS_PER_THREAD;
    const int threads = 256;
    const int blocks = (int)((groups + threads - 1) / threads);
    pc_kernel<<<blocks, threads>>>(x, Wleaf, W2, out, B);
}

// round 3
// speedup vs baseline: 1.6639x; 1.6639x over previous
#include <cuda_runtime.h>
#include <cstdint>

// naivePC: DP over (k,m) lattice, K=8, N=20.
// Column-sweep: S(k,m) = w0[k][m]*S(k,m-1) + w1[k][m]*S(k-1,m-1)*x[m-1]
// base S(k,k) = prod of first k bits; leaf S(1,m) = [popcnt(bits[0:m])==1]*wsm[m][idx]

#define NCOL 20
#define KMAX 8
#define RPT 4                 // rows per thread
#define THREADS 256
#define ROWS_PER_BLOCK (THREADS * RPT)   // 1024

__global__ __launch_bounds__(THREADS)
void pc_kernel(const unsigned char* __restrict__ xb,
               const float* __restrict__ Wleaf,   // [21][20]
               const float* __restrict__ W2,      // [9][21][2]
               float* __restrict__ out,
               int B)
{
    __shared__ float  s_wsm[21 * 32];     // stride 32: conflict-free dynamic gather
    __shared__ float2 s_w01[9 * 21];      // (w0,w1) pairs -> LDS.64
    __shared__ int    s_elem4;
    __shared__ uint4  s_stage[ROWS_PER_BLOCK * 20 / 16];  // 20KB staging (5120 words)

    const int tid = threadIdx.x;

    // ---- cooperative weight precompute (tiny, per block) ----
    if (tid < 21) {
        int m = tid;
        float mx = -1e30f;
        for (int i = 0; i < m; i++) mx = fmaxf(mx, Wleaf[m * 20 + i]);
        float Z = 0.0f;
        for (int i = 0; i < m; i++) Z += expf(Wleaf[m * 20 + i] - mx);
        float inv = (m > 0) ? (1.0f / Z) : 0.0f;
        for (int i = 0; i < 32; i++) {
            float v = 0.0f;
            if (i < m) v = expf(Wleaf[m * 20 + i] - mx) * inv;
            s_wsm[m * 32 + i] = v;
        }
    }
    if (tid >= 32 && tid < 32 + 9 * 21) {
        int j = tid - 32;
        float a = W2[j * 2 + 0];
        float b = W2[j * 2 + 1];
        float mx = fmaxf(a, b);
        float e0 = expf(a - mx), e1 = expf(b - mx);
        float inv = 1.0f / (e0 + e1);
        s_w01[j] = make_float2(e0 * inv, e1 * inv);
    }
    // ---- dtype detection from first 128 bytes (warp 7; L2-hit for all blocks) ----
    if (tid >= 224) {
        int lane = tid - 224;
        unsigned w = reinterpret_cast<const unsigned*>(xb)[lane];
        unsigned gt1 = __ballot_sync(0xFFFFFFFFu, (w & 0xFEFEFEFEu) != 0u); // any byte>1 -> float
        unsigned hi  = __ballot_sync(0xFFFFFFFFu, (w & 0xFFFFFF00u) != 0u); // nonzero upper bytes -> bool
        if (lane == 0) s_elem4 = (gt1 != 0u || hi == 0u) ? 1 : 0;
    }
    __syncthreads();

    const int elem4 = s_elem4;
    const long rowBase = (long)blockIdx.x * ROWS_PER_BLOCK;
    const bool fullBlock = (rowBase + ROWS_PER_BLOCK) <= (long)B;

    // ---- build 20-bit masks for 4 rows; thread owns rows rowBase + r*256 + tid ----
    unsigned mask[RPT] = {0, 0, 0, 0};

    if (elem4 && fullBlock) {
        // 4 chunks of 256 rows; coalesced uint4 staging + conflict-free LDS.128 readback
        #pragma unroll
        for (int c = 0; c < RPT; c++) {
            const uint4* src = reinterpret_cast<const uint4*>(xb) + (rowBase + (long)c * THREADS) * 5;
            #pragma unroll
            for (int j = 0; j < 5; j++)
                s_stage[tid + THREADS * j] = src[tid + THREADS * j];
            __syncthreads();
            unsigned mres = 0;
            #pragma unroll
            for (int j = 0; j < 5; j++) {
                uint4 q = s_stage[tid * 5 + j];
                mres |= (unsigned)(q.x != 0u) << (4 * j + 0);
                mres |= (unsigned)(q.y != 0u) << (4 * j + 1);
                mres |= (unsigned)(q.z != 0u) << (4 * j + 2);
                mres |= (unsigned)(q.w != 0u) << (4 * j + 3);
            }
            mask[c] = mres;
            __syncthreads();
        }
    } else if (!elem4 && fullBlock) {
        // bool bytes: stage whole block's 20KB once, conflict-free LDS.32 readback
        {
            const uint4* src = reinterpret_cast<const uint4*>(xb + rowBase * 20);
            #pragma unroll
            for (int j = 0; j < 5; j++)
                s_stage[tid + THREADS * j] = src[tid + THREADS * j];
        }
        __syncthreads();
        const unsigned* sw = reinterpret_cast<const unsigned*>(s_stage);
        #pragma unroll
        for (int r = 0; r < RPT; r++) {
            int rl = r * THREADS + tid;
            unsigned mres = 0;
            #pragma unroll
            for (int j = 0; j < 5; j++) {
                unsigned b = sw[rl * 5 + j] & 0x01010101u;
                unsigned nib = ((b * 0x01020408u) >> 24) & 0xFu;
                mres |= nib << (4 * j);
            }
            mask[r] = mres;
        }
        __syncthreads();
    } else {
        // tail block: guarded scalar path
        #pragma unroll
        for (int r = 0; r < RPT; r++) {
            long row = rowBase + (long)r * THREADS + tid;
            unsigned mres = 0;
            if (row < (long)B) {
                if (elem4) {
                    const unsigned* p = reinterpret_cast<const unsigned*>(xb);
                    for (int m = 0; m < 20; m++)
                        mres |= (unsigned)(p[row * 20 + m] != 0u) << m;
                } else {
                    for (int m = 0; m < 20; m++)
                        mres |= (unsigned)(xb[row * 20 + m] & 1) << m;
                }
            }
            mask[r] = mres;
        }
    }

    // ---- column-sweep DP, 4 rows interleaved ----
    float S[RPT][KMAX + 1];
    #pragma unroll
    for (int r = 0; r < RPT; r++)
        #pragma unroll
        for (int k = 0; k <= KMAX; k++) S[r][k] = 0.0f;

    int cnt[RPT] = {0, 0, 0, 0};
    int idx[RPT] = {0, 0, 0, 0};
    unsigned pf[RPT] = {1u, 1u, 1u, 1u};

    #pragma unroll
    for (int m = 1; m <= NCOL; m++) {
        unsigned bit[RPT];
        #pragma unroll
        for (int r = 0; r < RPT; r++) {
            bit[r] = (mask[r] >> (m - 1)) & 1u;
            cnt[r] += (int)bit[r];
            idx[r] = bit[r] ? (m - 1) : idx[r];
        }
        if (m <= KMAX) {
            #pragma unroll
            for (int r = 0; r < RPT; r++) pf[r] &= bit[r];
        }

        const int kmax = (m < KMAX) ? m : KMAX;
        #pragma unroll
        for (int k = KMAX; k >= 2; k--) {
            if (k > kmax) continue;              // folds at compile time
            if (k == m) {
                #pragma unroll
                for (int r = 0; r < RPT; r++)
                    S[r][k] = pf[r] ? 1.0f : 0.0f;
            } else {
                const float2 w = s_w01[k * 21 + m];
                #pragma unroll
                for (int r = 0; r < RPT; r++) {
                    float u = w.x * S[r][k];
                    S[r][k] = bit[r] ? fmaf(w.y, S[r][k - 1], u) : u;
                }
            }
        }
        // leaf S(1,m) — written AFTER its use at this column
        #pragma unroll
        for (int r = 0; r < RPT; r++) {
            float s = s_wsm[m * 32 + idx[r]];
            S[r][1] = (cnt[r] == 1) ? s : 0.0f;
        }
    }

    #pragma unroll
    for (int r = 0; r < RPT; r++) {
        long row = rowBase + (long)r * THREADS + tid;
        if (row < (long)B) out[row] = S[r][KMAX];
    }
}

extern "C" void kernel_launch(void* const* d_in, const int* in_sizes, int n_in,
                              void* d_out, int out_size)
{
    const unsigned char* x = (const unsigned char*)d_in[0];
    const float* Wleaf = (const float*)d_in[1];
    const float* W2 = (const float*)d_in[2];
    float* out = (float*)d_out;

    const int B = in_sizes[0] / NCOL;
    const int blocks = (B + ROWS_PER_BLOCK - 1) / ROWS_PER_BLOCK;

    pc_kernel<<<blocks, THREADS>>>(x, Wleaf, W2, out, B);
}